// round 14
// baseline (speedup 1.0000x reference)
#include <cuda_runtime.h>
#include <cuda_bf16.h>

// Problem constants (HGAT_9543417332149): B=8, N=2048, E=64, F=NH=64, FC=2*NH=128
#define BB 8
#define NN 2048
#define EE 64
#define FF 64
#define FC 128
#define WP 68      // padded stride (float4-aligned, conflict-free per 8-lane phase)
#define ACAP 256   // adjacency list capacity per node (deg ~21; guarded fallback)

// -------- device scratch (no allocations allowed) --------
__device__ float g_h[BB * NN * FF];     // h = x @ W
__device__ float g_xw[BB * NN * FF];    // x @ W_ind
__device__ float g_s[BB * NN];          // leaky_relu(h @ a_node)
__device__ float g_hn[BB * NN];         // h @ a_gn
__device__ float g_agg[BB * EE * FF];   // hyperedge embedding (raw, pre-elu)
__device__ float g_ge[BB * EE];         // agg @ a_ge
__device__ float g_se[BB * EE];         // edge scores from elu(agg)
__device__ float g_ind[BB * NN * FF];   // industry features
__device__ int   g_emem[EE * NN];       // per-edge member node lists
__device__ int   g_ecnt[EE];            // per-edge member counts
__device__ int   g_alist[NN * ACAP];    // per-node neighbor lists
__device__ int   g_acnt[NN];            // per-node neighbor counts

// fast tanh: 1 - 2/(e^{2x}+1); clamp keeps __fdividef divisor finite.
__device__ __forceinline__ float ftanh(float x)
{
    x = fminf(fmaxf(x, -10.f), 10.f);
    float e = __expf(2.f * x);
    return 1.f - __fdividef(2.f, e + 1.f);
}

// =======================================================================
// K1 (fused): blocks 0..255   -> adj compaction (DRAM stream starts at t=0)
//             blocks 256..263 -> per-edge member lists (1 warp / edge)
//             blocks 264..775 -> h/xw GEMM + s/hn via register reductions
// =======================================================================
__global__ __launch_bounds__(256, 4) void k_h_emem(const float* __restrict__ x,
                                                   const float* __restrict__ H,
                                                   const float* __restrict__ adj,
                                                   const float* __restrict__ W,
                                                   const float* __restrict__ Wi,
                                                   const float* __restrict__ a_node,
                                                   const float* __restrict__ a_gn)
{
    __shared__ float sWt[FF * WP];   // sWt[f*WP+k] = W[k][f]
    __shared__ float sWit[FF * WP];
    __shared__ float sx[32 * WP];    // sx[r*WP+k]
    __shared__ float red_s[8][8], red_g[8][8];

    int tid = threadIdx.x;
    int wid = tid >> 5, lane = tid & 31;

    if (blockIdx.x < 256) {
        // ---- adj compaction: warp/row, float4 + warp prefix scan ----
        int n = (int)blockIdx.x * 8 + wid;
        const float4* row4 = (const float4*)(adj + (long)n * NN);
        int cnt = 0;
        #pragma unroll 1
        for (int it = 0; it < 16; ++it) {
            float4 v = row4[it * 32 + lane];
            int b0 = v.x > 0.f, b1 = v.y > 0.f, b2 = v.z > 0.f, b3 = v.w > 0.f;
            int pop = b0 + b1 + b2 + b3;
            int s = pop;
            #pragma unroll
            for (int o = 1; o < 32; o <<= 1) {
                int t = __shfl_up_sync(0xffffffffu, s, o);
                if (lane >= o) s += t;
            }
            int off = cnt + s - pop;                 // exclusive, ascending m
            int m0 = (it * 32 + lane) * 4;
            if (b0) { if (off < ACAP) g_alist[n * ACAP + off] = m0;     ++off; }
            if (b1) { if (off < ACAP) g_alist[n * ACAP + off] = m0 + 1; ++off; }
            if (b2) { if (off < ACAP) g_alist[n * ACAP + off] = m0 + 2; ++off; }
            if (b3) { if (off < ACAP) g_alist[n * ACAP + off] = m0 + 3; ++off; }
            cnt += __shfl_sync(0xffffffffu, s, 31);
        }
        if (lane == 0) g_acnt[n] = cnt;
        return;
    }

    if (blockIdx.x < 264) {
        // ---- member-list compaction: warp handles one edge ----
        int e = (int)(blockIdx.x - 256) * 8 + wid;
        int cnt = 0;
        for (int base = 0; base < NN; base += 32) {
            int n = base + lane;
            bool m = H[n * EE + e] > 0.f;
            unsigned bm = __ballot_sync(0xffffffffu, m);
            if (m) g_emem[e * NN + cnt + __popc(bm & ((1u << lane) - 1u))] = n;
            cnt += __popc(bm);
        }
        if (lane == 0) g_ecnt[e] = cnt;
        return;
    }

    // ================= GEMM blocks =================
    int f = tid & 63, grp = tid >> 6;
    float an = __ldg(&a_node[f]);
    float ag = __ldg(&a_gn[f]);

    // load W/Wi transposed: sWt[f][k] = W[k][f]
    for (int i = tid; i < FF * FF; i += 256) {
        int k = i >> 6, ff = i & 63;
        sWt[ff * WP + k]  = W[i];
        sWit[ff * WP + k] = Wi[i];
    }
    long pbase = (long)(blockIdx.x - 264) * 32;
    for (int i = tid; i < 32 * FF; i += 256)
        sx[(i >> 6) * WP + (i & 63)] = x[(pbase + (i >> 6)) * FF + (i & 63)];
    __syncthreads();

    // ---- mainloop: thread owns column f, 8 row-accumulators x 2 matrices
    const float4* wq  = (const float4*)&sWt[f * WP];
    const float4* wiq = (const float4*)&sWit[f * WP];
    const float*  sxg = &sx[(grp * 8) * WP];

    float accH[8], accX[8];
    #pragma unroll
    for (int r = 0; r < 8; ++r) { accH[r] = 0.f; accX[r] = 0.f; }

    #pragma unroll 4
    for (int kq = 0; kq < 16; ++kq) {
        float4 w  = wq[kq];
        float4 wi = wiq[kq];
        #pragma unroll
        for (int r = 0; r < 8; ++r) {
            float4 xv = *(const float4*)&sxg[r * WP + kq * 4];  // warp-uniform broadcast
            accH[r] += xv.x * w.x  + xv.y * w.y  + xv.z * w.z  + xv.w * w.w;
            accX[r] += xv.x * wi.x + xv.y * wi.y + xv.z * wi.z + xv.w * wi.w;
        }
    }
    #pragma unroll
    for (int r = 0; r < 8; ++r) {
        long pair = pbase + grp * 8 + r;
        g_h[pair * FF + f]  = accH[r];
        g_xw[pair * FF + f] = accX[r];
    }

    // ---- s/hn from register-resident h: warp shuffle partials ----
    // row grp*8+r spans warps 2*grp (f 0..31) and 2*grp+1 (f 32..63)
    #pragma unroll
    for (int r = 0; r < 8; ++r) {
        float ps = accH[r] * an;
        float pg = accH[r] * ag;
        #pragma unroll
        for (int o = 16; o; o >>= 1) {
            ps += __shfl_xor_sync(0xffffffffu, ps, o);
            pg += __shfl_xor_sync(0xffffffffu, pg, o);
        }
        if (lane == 0) { red_s[wid][r] = ps; red_g[wid][r] = pg; }
    }
    __syncthreads();
    if (tid < 32) {
        int g2 = tid >> 3, r = tid & 7;           // row = g2*8 + r
        long pair = pbase + g2 * 8 + r;
        float s = red_s[2 * g2][r] + red_s[2 * g2 + 1][r];
        g_s[pair] = (s >= 0.f) ? s : 0.2f * s;
        g_hn[pair] = red_g[2 * g2][r] + red_g[2 * g2 + 1][r];
    }
}

// =======================================================================
// K2 (fused): blocks 0..2047   -> industry gather from precompacted lists
//             blocks 2048..2559 -> per-(b,e) edge softmax/agg/scores
// =======================================================================
struct SmInd  { int slist[ACAP]; };
struct SmEdge { float red[16]; float swv[512]; float sagg[FF]; float selu[FF]; float comb[512]; };
union SmU { SmInd ind; SmEdge edge; };

__global__ __launch_bounds__(512) void k_ind_edge(const float* __restrict__ adj,
                                                  const float* __restrict__ a_ge,
                                                  const float* __restrict__ fcW,
                                                  const float* __restrict__ fcb,
                                                  const float* __restrict__ av)
{
    __shared__ SmU sm;
    int tid = threadIdx.x;
    int wid = tid >> 5, lane = tid & 31;

    if (blockIdx.x < 2048) {
        // ================= industry gather =================
        int n = blockIdx.x;
        int b = tid >> 6, f = tid & 63;
        int cnt = g_acnt[n];
        const float* xwb = g_xw + (long)b * NN * FF + f;

        if (cnt <= ACAP) {
            for (int i = tid; i < cnt; i += 512) sm.ind.slist[i] = g_alist[n * ACAP + i];
            __syncthreads();

            float acc = 0.f;
            for (int i = 0; i < cnt; i += 8) {
                int   id[8];
                float v[8];
                #pragma unroll
                for (int j = 0; j < 8; ++j) id[j] = (i + j < cnt) ? sm.ind.slist[i + j] : sm.ind.slist[0];
                #pragma unroll
                for (int j = 0; j < 8; ++j) v[j] = xwb[(long)id[j] * FF];
                #pragma unroll
                for (int j = 0; j < 8; ++j) if (i + j < cnt) acc += v[j];
            }
            float d = (cnt < 1) ? 1.f : (float)cnt;
            g_ind[((long)b * NN + n) * FF + f] = acc / d;
        } else {
            // never-taken safety fallback: direct row scan, ascending m
            const float* row = adj + (long)n * NN;
            float acc = 0.f;
            for (int m = 0; m < NN; ++m)
                if (row[m] > 0.f) acc += xwb[(long)m * FF];
            g_ind[((long)b * NN + n) * FF + f] = acc / (float)cnt;
        }
        return;
    }

    // ================= edge path =================
    int idx = (int)blockIdx.x - 2048;
    int e = idx & 63, b = idx >> 6;
    int M = g_ecnt[e];

    if (M == 0) {
        if (tid < FF) g_agg[((b * EE) + e) * FF + tid] = 0.f;
        if (tid == 0) { g_ge[b * EE + e] = 0.f; g_se[b * EE + e] = 0.f; }
        return;
    }

    const int*   mem = &g_emem[e * NN];
    const float* sb  = &g_s[b * NN];

    // ---- max over member scores ----
    float mx = -1e30f;
    for (int i = tid; i < M; i += 512) mx = fmaxf(mx, sb[mem[i]]);
    #pragma unroll
    for (int o = 16; o; o >>= 1) mx = fmaxf(mx, __shfl_xor_sync(0xffffffffu, mx, o));
    if (lane == 0) sm.edge.red[wid] = mx;
    __syncthreads();
    float maxv = sm.edge.red[0];
    #pragma unroll
    for (int w2 = 1; w2 < 16; ++w2) maxv = fmaxf(maxv, sm.edge.red[w2]);
    __syncthreads();

    // ---- sum of exp; stash weights ----
    float ps = 0.f;
    for (int i = tid; i < M; i += 512) {
        float w = __expf(sb[mem[i]] - maxv);
        if (i < 512) sm.edge.swv[i] = w;
        ps += w;
    }
    #pragma unroll
    for (int o = 16; o; o >>= 1) ps += __shfl_xor_sync(0xffffffffu, ps, o);
    if (lane == 0) sm.edge.red[wid] = ps;
    __syncthreads();
    float ssum = 0.f;
    #pragma unroll
    for (int w2 = 0; w2 < 16; ++w2) ssum += sm.edge.red[w2];
    float inv = 1.f / ssum;

    // ---- agg[f] = sum_i alpha_i h[b, m_i, f] (8-way member split) ----
    int f = tid & 63, q = tid >> 6;
    float acc = 0.f;
    for (int i = q; i < M; i += 8) {
        float w = (i < 512) ? sm.edge.swv[i] : __expf(sb[mem[i]] - maxv);
        acc += w * g_h[((long)b * NN + mem[i]) * FF + f];
    }
    sm.edge.comb[tid] = acc;
    __syncthreads();
    if (tid < FF) {
        float a = 0.f;
        #pragma unroll
        for (int j = 0; j < 8; ++j) a += sm.edge.comb[tid + 64 * j];
        a *= inv;
        sm.edge.sagg[tid] = a;
        g_agg[((b * EE) + e) * FF + tid] = a;
        sm.edge.selu[tid] = (a > 0.f) ? a : expm1f(a);
    }
    __syncthreads();

    // ---- ge = agg . a_ge (threads 0..63) ----
    float pg = (tid < FF) ? sm.edge.sagg[tid] * a_ge[tid] : 0.f;
    #pragma unroll
    for (int o = 16; o; o >>= 1) pg += __shfl_xor_sync(0xffffffffu, pg, o);
    __syncthreads();
    if (tid < 64 && lane == 0) sm.edge.red[wid] = pg;
    __syncthreads();
    if (tid == 0) g_ge[b * EE + e] = sm.edge.red[0] + sm.edge.red[1];

    // ---- se = tanh(elu(agg) @ fcW + fcb) . av  (threads 0..127) ----
    float pv = 0.f;
    if (tid < FC) {
        float z = fcb[tid];
        #pragma unroll
        for (int f2 = 0; f2 < FF; ++f2) z += sm.edge.selu[f2] * __ldg(&fcW[f2 * FC + tid]);
        pv = av[tid] * ftanh(z);
    }
    #pragma unroll
    for (int o = 16; o; o >>= 1) pv += __shfl_xor_sync(0xffffffffu, pv, o);
    __syncthreads();
    if (tid < 128 && lane == 0) sm.edge.red[wid] = pv;
    __syncthreads();
    if (tid == 0) g_se[b * EE + e] = sm.edge.red[0] + sm.edge.red[1] + sm.edge.red[2] + sm.edge.red[3];
}

// =======================================================================
// K3: one WARP per (b,n) pair. 512 threads = 16 pairs/block.
// =======================================================================
__global__ __launch_bounds__(512) void k_final(const float* __restrict__ Hm,
                                               const float* __restrict__ fcW,
                                               const float* __restrict__ fcb,
                                               const float* __restrict__ av,
                                               float* __restrict__ out)
{
    __shared__ float sfc[FF * FC];     // 32 KB
    __shared__ float sfcb[FC], sav[FC];
    __shared__ float2 swig[16][FF];    // per-warp (industry, g) interleaved

    int tid = threadIdx.x, w = tid >> 5, lane = tid & 31;
    for (int i = tid; i < FF * FC; i += 512) sfc[i] = fcW[i];
    if (tid < FC) { sfcb[tid] = fcb[tid]; sav[tid] = av[tid]; }
    __syncthreads();

    long pair = (long)blockIdx.x * 16 + w;
    int b = (int)(pair >> 11), n = (int)(pair & 2047);
    int f0 = lane, f1 = lane + 32;

    float ind0 = g_ind[pair * FF + f0], ind1 = g_ind[pair * FF + f1];
    float h0   = g_h[pair * FF + f0],   h1   = g_h[pair * FF + f1];
    float hnv  = g_hn[pair];

    bool m0 = Hm[(long)n * EE + lane] > 0.f;
    bool m1 = Hm[(long)n * EE + lane + 32] > 0.f;
    unsigned mask0 = __ballot_sync(0xffffffffu, m0);
    unsigned mask1 = __ballot_sync(0xffffffffu, m1);
    float se0 = m0 ? g_se[b * EE + lane]      : -1e30f;
    float se1 = m1 ? g_se[b * EE + lane + 32] : -1e30f;
    float mx = fmaxf(se0, se1);
    #pragma unroll
    for (int o = 16; o; o >>= 1) mx = fmaxf(mx, __shfl_xor_sync(0xffffffffu, mx, o));
    float ex0 = m0 ? __expf(se0 - mx) : 0.f;
    float ex1 = m1 ? __expf(se1 - mx) : 0.f;
    float sum = ex0 + ex1;
    #pragma unroll
    for (int o = 16; o; o >>= 1) sum += __shfl_xor_sync(0xffffffffu, sum, o);
    float inv = 1.f / sum;
    float c0 = ex0 * inv, c1 = ex1 * inv;
    float bt0 = m0 ? __fdividef(1.f, 1.f + __expf(-(hnv + g_ge[b * EE + lane])))      : 0.f;
    float bt1 = m1 ? __fdividef(1.f, 1.f + __expf(-(hnv + g_ge[b * EE + lane + 32]))) : 0.f;

    // ---- g[f] = sum over member edges only (ballot-driven, ~2.9 iters) ----
    float gv0 = 0.f, gv1 = 0.f;
    const float* aggb = g_agg + ((long)b * EE) * FF;
    while (mask0) {
        int e = __ffs(mask0) - 1; mask0 &= mask0 - 1;
        float ce = __shfl_sync(0xffffffffu, c0, e);
        float bt = __shfl_sync(0xffffffffu, bt0, e);
        float a0 = aggb[e * FF + f0], a1 = aggb[e * FF + f1];
        float v0 = fmaf(bt, h0 - a0, a0);
        float v1 = fmaf(bt, h1 - a1, a1);
        gv0 += ce * ((v0 > 0.f) ? v0 : expm1f(v0));
        gv1 += ce * ((v1 > 0.f) ? v1 : expm1f(v1));
    }
    while (mask1) {
        int e = __ffs(mask1) - 1; mask1 &= mask1 - 1;
        float ce = __shfl_sync(0xffffffffu, c1, e);
        float bt = __shfl_sync(0xffffffffu, bt1, e);
        int eg = e + 32;
        float a0 = aggb[eg * FF + f0], a1 = aggb[eg * FF + f1];
        float v0 = fmaf(bt, h0 - a0, a0);
        float v1 = fmaf(bt, h1 - a1, a1);
        gv0 += ce * ((v0 > 0.f) ? v0 : expm1f(v0));
        gv1 += ce * ((v1 > 0.f) ? v1 : expm1f(v1));
    }

    swig[w][f0] = make_float2(ind0, gv0);
    swig[w][f1] = make_float2(ind1, gv1);
    __syncwarp();

    float z1[4], z2[4];
    #pragma unroll
    for (int j = 0; j < 4; ++j) { z1[j] = sfcb[lane * 4 + j]; z2[j] = z1[j]; }
    #pragma unroll 4
    for (int f2 = 0; f2 < FF; ++f2) {
        float2 ig = swig[w][f2];
        float4 wv = *(const float4*)&sfc[f2 * FC + lane * 4];
        z1[0] += ig.x * wv.x; z1[1] += ig.x * wv.y; z1[2] += ig.x * wv.z; z1[3] += ig.x * wv.w;
        z2[0] += ig.y * wv.x; z2[1] += ig.y * wv.y; z2[2] += ig.y * wv.z; z2[3] += ig.y * wv.w;
    }
    float p1 = 0.f, p2 = 0.f;
    #pragma unroll
    for (int j = 0; j < 4; ++j) {
        float a = sav[lane * 4 + j];
        p1 += a * ftanh(z1[j]);
        p2 += a * ftanh(z2[j]);
    }
    #pragma unroll
    for (int o = 16; o; o >>= 1) {
        p1 += __shfl_xor_sync(0xffffffffu, p1, o);
        p2 += __shfl_xor_sync(0xffffffffu, p2, o);
    }

    float mm = fmaxf(p1, p2);
    float q1 = __expf(p1 - mm), q2 = __expf(p2 - mm);
    float cc = q1 / (q1 + q2);
    out[pair * FF + f0] = fmaf(cc, ind0 - gv0, gv0);
    out[pair * FF + f1] = fmaf(cc, ind1 - gv1, gv1);
}

// =======================================================================
// launcher
// =======================================================================
extern "C" void kernel_launch(void* const* d_in, const int* in_sizes, int n_in,
                              void* d_out, int out_size)
{
    const float* x   = (const float*)d_in[0];
    const float* H   = (const float*)d_in[1];
    const float* adj = (const float*)d_in[2];
    int wb = (n_in >= 12 && in_sizes[3] == 1) ? 4 : 3;
    const float* W      = (const float*)d_in[wb + 0];
    const float* W_ind  = (const float*)d_in[wb + 1];
    const float* a_node = (const float*)d_in[wb + 2];
    const float* a_gn   = (const float*)d_in[wb + 3];
    const float* a_ge   = (const float*)d_in[wb + 4];
    const float* fcW    = (const float*)d_in[wb + 5];
    const float* fcb    = (const float*)d_in[wb + 6];
    const float* av     = (const float*)d_in[wb + 7];
    float* out = (float*)d_out;

    k_h_emem<<<264 + 512, 256>>>(x, H, adj, W, W_ind, a_node, a_gn);
    k_ind_edge<<<2048 + EE * BB, 512>>>(adj, a_ge, fcW, fcb, av);
    k_final<<<(BB * NN) / 16, 512>>>(H, fcW, fcb, av, out);
}

// round 15
// speedup vs baseline: 1.0903x; 1.0903x over previous
#include <cuda_runtime.h>
#include <cuda_bf16.h>

// Problem constants (HGAT_9543417332149): B=8, N=2048, E=64, F=NH=64, FC=2*NH=128
#define BB 8
#define NN 2048
#define EE 64
#define FF 64
#define FC 128
#define WP 68      // padded stride (16B-aligned rows, conflict-free per 8-lane phase)
#define ACAP 256   // adjacency list capacity per node (deg ~21; guarded fallback)

// -------- device scratch (no allocations allowed) --------
__device__ float g_h[BB * NN * FF];     // h = x @ W
__device__ float g_xw[BB * NN * FF];    // x @ W_ind
__device__ float g_s[BB * NN];          // leaky_relu(h @ a_node)
__device__ float g_hn[BB * NN];         // h @ a_gn
__device__ float g_agg[BB * EE * FF];   // hyperedge embedding (raw, pre-elu)
__device__ float g_ge[BB * EE];         // agg @ a_ge
__device__ float g_se[BB * EE];         // edge scores from elu(agg)
__device__ int   g_emem[EE * NN];       // per-edge member node lists
__device__ int   g_ecnt[EE];            // per-edge member counts
__device__ int   g_alist[NN * ACAP];    // per-node neighbor lists
__device__ int   g_acnt[NN];            // per-node neighbor counts

typedef unsigned long long u64t;

// packed 2-wide fp32 FMA (Blackwell f32x2) — ptxas never auto-fuses this
__device__ __forceinline__ u64t ffma2(u64t a, u64t b, u64t c)
{
    u64t d;
    asm("fma.rn.f32x2 %0, %1, %2, %3;" : "=l"(d) : "l"(a), "l"(b), "l"(c));
    return d;
}
__device__ __forceinline__ float2 unpk(u64t v)
{
    float2 r;
    asm("mov.b64 {%0, %1}, %2;" : "=f"(r.x), "=f"(r.y) : "l"(v));
    return r;
}

// fast tanh: 1 - 2/(e^{2x}+1); clamp keeps __fdividef divisor finite.
__device__ __forceinline__ float ftanh(float x)
{
    x = fminf(fmaxf(x, -10.f), 10.f);
    float e = __expf(2.f * x);
    return 1.f - __fdividef(2.f, e + 1.f);
}

// =======================================================================
// K1 (fused): blocks 0..255   -> adj compaction (DRAM stream starts at t=0)
//             blocks 256..263 -> per-edge member lists (1 warp / edge)
//             blocks 264..775 -> h/xw GEMM (packed FFMA2) + s/hn reductions
// =======================================================================
__global__ __launch_bounds__(256, 4) void k_h_emem(const float* __restrict__ x,
                                                   const float* __restrict__ H,
                                                   const float* __restrict__ adj,
                                                   const float* __restrict__ W,
                                                   const float* __restrict__ Wi,
                                                   const float* __restrict__ a_node,
                                                   const float* __restrict__ a_gn)
{
    __shared__ __align__(16) float sWt[FF * WP];   // sWt[f*WP+k] = W[k][f]
    __shared__ __align__(16) float sWit[FF * WP];
    __shared__ __align__(16) float sx[32 * WP];    // sx[r*WP+k]
    __shared__ float red_s[8][8], red_g[8][8];

    int tid = threadIdx.x;
    int wid = tid >> 5, lane = tid & 31;

    if (blockIdx.x < 256) {
        // ---- adj compaction: warp/row, float4 + warp prefix scan ----
        int n = (int)blockIdx.x * 8 + wid;
        const float4* row4 = (const float4*)(adj + (long)n * NN);
        int cnt = 0;
        #pragma unroll 1
        for (int it = 0; it < 16; ++it) {
            float4 v = row4[it * 32 + lane];
            int b0 = v.x > 0.f, b1 = v.y > 0.f, b2 = v.z > 0.f, b3 = v.w > 0.f;
            int pop = b0 + b1 + b2 + b3;
            int s = pop;
            #pragma unroll
            for (int o = 1; o < 32; o <<= 1) {
                int t = __shfl_up_sync(0xffffffffu, s, o);
                if (lane >= o) s += t;
            }
            int off = cnt + s - pop;                 // exclusive, ascending m
            int m0 = (it * 32 + lane) * 4;
            if (b0) { if (off < ACAP) g_alist[n * ACAP + off] = m0;     ++off; }
            if (b1) { if (off < ACAP) g_alist[n * ACAP + off] = m0 + 1; ++off; }
            if (b2) { if (off < ACAP) g_alist[n * ACAP + off] = m0 + 2; ++off; }
            if (b3) { if (off < ACAP) g_alist[n * ACAP + off] = m0 + 3; ++off; }
            cnt += __shfl_sync(0xffffffffu, s, 31);
        }
        if (lane == 0) g_acnt[n] = cnt;
        return;
    }

    if (blockIdx.x < 264) {
        // ---- member-list compaction: warp handles one edge ----
        int e = (int)(blockIdx.x - 256) * 8 + wid;
        int cnt = 0;
        for (int base = 0; base < NN; base += 32) {
            int n = base + lane;
            bool m = H[n * EE + e] > 0.f;
            unsigned bm = __ballot_sync(0xffffffffu, m);
            if (m) g_emem[e * NN + cnt + __popc(bm & ((1u << lane) - 1u))] = n;
            cnt += __popc(bm);
        }
        if (lane == 0) g_ecnt[e] = cnt;
        return;
    }

    // ================= GEMM blocks =================
    int f = tid & 63, grp = tid >> 6;
    float an = __ldg(&a_node[f]);
    float ag = __ldg(&a_gn[f]);

    // load W/Wi transposed: sWt[f][k] = W[k][f]
    for (int i = tid; i < FF * FF; i += 256) {
        int k = i >> 6, ff = i & 63;
        sWt[ff * WP + k]  = W[i];
        sWit[ff * WP + k] = Wi[i];
    }
    long pbase = (long)(blockIdx.x - 264) * 32;
    for (int i = tid; i < 32 * FF; i += 256)
        sx[(i >> 6) * WP + (i & 63)] = x[(pbase + (i >> 6)) * FF + (i & 63)];
    __syncthreads();

    // ---- mainloop: packed f32x2 along k; 8 row-accumulators x 2 matrices
    const ulonglong2* wq  = (const ulonglong2*)&sWt[f * WP];
    const ulonglong2* wiq = (const ulonglong2*)&sWit[f * WP];
    const float*      sxg = &sx[(grp * 8) * WP];

    u64t accH[8], accX[8];
    #pragma unroll
    for (int r = 0; r < 8; ++r) { accH[r] = 0ull; accX[r] = 0ull; }

    #pragma unroll 4
    for (int kq = 0; kq < 16; ++kq) {
        ulonglong2 w  = wq[kq];   // (w[k..k+1], w[k+2..k+3]) packed pairs
        ulonglong2 wi = wiq[kq];
        #pragma unroll
        for (int r = 0; r < 8; ++r) {
            ulonglong2 xv = *(const ulonglong2*)&sxg[r * WP + kq * 4];  // LDS.128 broadcast
            accH[r] = ffma2(xv.x, w.x,  accH[r]);
            accH[r] = ffma2(xv.y, w.y,  accH[r]);
            accX[r] = ffma2(xv.x, wi.x, accX[r]);
            accX[r] = ffma2(xv.y, wi.y, accX[r]);
        }
    }
    float hrow[8];
    #pragma unroll
    for (int r = 0; r < 8; ++r) {
        long pair = pbase + grp * 8 + r;
        float2 th = unpk(accH[r]);
        float2 tx = unpk(accX[r]);
        hrow[r] = th.x + th.y;
        g_h[pair * FF + f]  = hrow[r];
        g_xw[pair * FF + f] = tx.x + tx.y;
    }

    // ---- s/hn from register-resident h: warp shuffle partials ----
    #pragma unroll
    for (int r = 0; r < 8; ++r) {
        float ps = hrow[r] * an;
        float pg = hrow[r] * ag;
        #pragma unroll
        for (int o = 16; o; o >>= 1) {
            ps += __shfl_xor_sync(0xffffffffu, ps, o);
            pg += __shfl_xor_sync(0xffffffffu, pg, o);
        }
        if (lane == 0) { red_s[wid][r] = ps; red_g[wid][r] = pg; }
    }
    __syncthreads();
    if (tid < 32) {
        int g2 = tid >> 3, r = tid & 7;           // row = g2*8 + r
        long pair = pbase + g2 * 8 + r;
        float s = red_s[2 * g2][r] + red_s[2 * g2 + 1][r];
        g_s[pair] = (s >= 0.f) ? s : 0.2f * s;
        g_hn[pair] = red_g[2 * g2][r] + red_g[2 * g2 + 1][r];
    }
}

// =======================================================================
// K2: per-(b,e) edge softmax/agg/scores only (industry moved to K3)
// =======================================================================
__global__ __launch_bounds__(512) void k_edge(const float* __restrict__ a_ge,
                                              const float* __restrict__ fcW,
                                              const float* __restrict__ fcb,
                                              const float* __restrict__ av)
{
    __shared__ float red[16];
    __shared__ float swv[512];
    __shared__ float sagg[FF], selu[FF];
    __shared__ float comb[512];

    int tid = threadIdx.x;
    int wid = tid >> 5, lane = tid & 31;
    int e = (int)blockIdx.x & 63, b = (int)blockIdx.x >> 6;
    int M = g_ecnt[e];

    if (M == 0) {
        if (tid < FF) g_agg[((b * EE) + e) * FF + tid] = 0.f;
        if (tid == 0) { g_ge[b * EE + e] = 0.f; g_se[b * EE + e] = 0.f; }
        return;
    }

    const int*   mem = &g_emem[e * NN];
    const float* sb  = &g_s[b * NN];

    // ---- max over member scores ----
    float mx = -1e30f;
    for (int i = tid; i < M; i += 512) mx = fmaxf(mx, sb[mem[i]]);
    #pragma unroll
    for (int o = 16; o; o >>= 1) mx = fmaxf(mx, __shfl_xor_sync(0xffffffffu, mx, o));
    if (lane == 0) red[wid] = mx;
    __syncthreads();
    float maxv = red[0];
    #pragma unroll
    for (int w2 = 1; w2 < 16; ++w2) maxv = fmaxf(maxv, red[w2]);
    __syncthreads();

    // ---- sum of exp; stash weights ----
    float ps = 0.f;
    for (int i = tid; i < M; i += 512) {
        float w = __expf(sb[mem[i]] - maxv);
        if (i < 512) swv[i] = w;
        ps += w;
    }
    #pragma unroll
    for (int o = 16; o; o >>= 1) ps += __shfl_xor_sync(0xffffffffu, ps, o);
    if (lane == 0) red[wid] = ps;
    __syncthreads();
    float ssum = 0.f;
    #pragma unroll
    for (int w2 = 0; w2 < 16; ++w2) ssum += red[w2];
    float inv = 1.f / ssum;

    // ---- agg[f] = sum_i alpha_i h[b, m_i, f] (8-way member split) ----
    int f = tid & 63, q = tid >> 6;
    float acc = 0.f;
    for (int i = q; i < M; i += 8) {
        float w = (i < 512) ? swv[i] : __expf(sb[mem[i]] - maxv);
        acc += w * g_h[((long)b * NN + mem[i]) * FF + f];
    }
    comb[tid] = acc;
    __syncthreads();
    if (tid < FF) {
        float a = 0.f;
        #pragma unroll
        for (int j = 0; j < 8; ++j) a += comb[tid + 64 * j];
        a *= inv;
        sagg[tid] = a;
        g_agg[((b * EE) + e) * FF + tid] = a;
        selu[tid] = (a > 0.f) ? a : expm1f(a);
    }
    __syncthreads();

    // ---- ge = agg . a_ge (threads 0..63) ----
    float pg = (tid < FF) ? sagg[tid] * a_ge[tid] : 0.f;
    #pragma unroll
    for (int o = 16; o; o >>= 1) pg += __shfl_xor_sync(0xffffffffu, pg, o);
    __syncthreads();
    if (tid < 64 && lane == 0) red[wid] = pg;
    __syncthreads();
    if (tid == 0) g_ge[b * EE + e] = red[0] + red[1];

    // ---- se = tanh(elu(agg) @ fcW + fcb) . av  (threads 0..127) ----
    float pv = 0.f;
    if (tid < FC) {
        float z = fcb[tid];
        #pragma unroll
        for (int f2 = 0; f2 < FF; ++f2) z += selu[f2] * __ldg(&fcW[f2 * FC + tid]);
        pv = av[tid] * ftanh(z);
    }
    #pragma unroll
    for (int o = 16; o; o >>= 1) pv += __shfl_xor_sync(0xffffffffu, pv, o);
    __syncthreads();
    if (tid < 128 && lane == 0) red[wid] = pv;
    __syncthreads();
    if (tid == 0) g_se[b * EE + e] = red[0] + red[1] + red[2] + red[3];
}

// =======================================================================
// K3: one WARP per (b,n) pair; industry gather fused in (L2-resident g_xw).
// =======================================================================
__global__ __launch_bounds__(512) void k_final(const float* __restrict__ Hm,
                                               const float* __restrict__ adj,
                                               const float* __restrict__ fcW,
                                               const float* __restrict__ fcb,
                                               const float* __restrict__ av,
                                               float* __restrict__ out)
{
    __shared__ float sfc[FF * FC];     // 32 KB
    __shared__ float sfcb[FC], sav[FC];
    __shared__ float2 swig[16][FF];    // per-warp (industry, g) interleaved

    int tid = threadIdx.x, w = tid >> 5, lane = tid & 31;
    for (int i = tid; i < FF * FC; i += 512) sfc[i] = fcW[i];
    if (tid < FC) { sfcb[tid] = fcb[tid]; sav[tid] = av[tid]; }
    __syncthreads();

    long pair = (long)blockIdx.x * 16 + w;
    int b = (int)(pair >> 11), n = (int)(pair & 2047);
    int f0 = lane, f1 = lane + 32;

    // ---- industry gather (starts early; latency overlaps everything below)
    int cnt = g_acnt[n];
    const float* xwb = g_xw + (long)b * NN * FF;
    float s0 = 0.f, s1 = 0.f;
    if (cnt <= ACAP) {
        const int* lst = &g_alist[n * ACAP];
        int i = 0;
        for (; i + 4 <= cnt; i += 4) {
            int m0 = lst[i], m1 = lst[i + 1], m2 = lst[i + 2], m3 = lst[i + 3];
            float a0 = xwb[(long)m0 * FF + f0], a1 = xwb[(long)m1 * FF + f0];
            float a2 = xwb[(long)m2 * FF + f0], a3 = xwb[(long)m3 * FF + f0];
            float c0 = xwb[(long)m0 * FF + f1], c1 = xwb[(long)m1 * FF + f1];
            float c2 = xwb[(long)m2 * FF + f1], c3 = xwb[(long)m3 * FF + f1];
            s0 += a0 + a1 + a2 + a3;
            s1 += c0 + c1 + c2 + c3;
        }
        for (; i < cnt; ++i) {
            int m = lst[i];
            s0 += xwb[(long)m * FF + f0];
            s1 += xwb[(long)m * FF + f1];
        }
    } else {
        // never-taken safety fallback: direct row scan, ascending m
        const float* row = adj + (long)n * NN;
        for (int m = 0; m < NN; ++m)
            if (row[m] > 0.f) { s0 += xwb[(long)m * FF + f0]; s1 += xwb[(long)m * FF + f1]; }
    }
    float dd = (cnt < 1) ? 1.f : (float)cnt;
    float ind0 = s0 / dd, ind1 = s1 / dd;

    float h0  = g_h[pair * FF + f0], h1 = g_h[pair * FF + f1];
    float hnv = g_hn[pair];

    bool m0 = Hm[(long)n * EE + lane] > 0.f;
    bool m1 = Hm[(long)n * EE + lane + 32] > 0.f;
    unsigned mask0 = __ballot_sync(0xffffffffu, m0);
    unsigned mask1 = __ballot_sync(0xffffffffu, m1);
    float se0 = m0 ? g_se[b * EE + lane]      : -1e30f;
    float se1 = m1 ? g_se[b * EE + lane + 32] : -1e30f;
    float mx = fmaxf(se0, se1);
    #pragma unroll
    for (int o = 16; o; o >>= 1) mx = fmaxf(mx, __shfl_xor_sync(0xffffffffu, mx, o));
    float ex0 = m0 ? __expf(se0 - mx) : 0.f;
    float ex1 = m1 ? __expf(se1 - mx) : 0.f;
    float sum = ex0 + ex1;
    #pragma unroll
    for (int o = 16; o; o >>= 1) sum += __shfl_xor_sync(0xffffffffu, sum, o);
    float inv = 1.f / sum;
    float c0 = ex0 * inv, c1 = ex1 * inv;
    float bt0 = m0 ? __fdividef(1.f, 1.f + __expf(-(hnv + g_ge[b * EE + lane])))      : 0.f;
    float bt1 = m1 ? __fdividef(1.f, 1.f + __expf(-(hnv + g_ge[b * EE + lane + 32]))) : 0.f;

    // ---- g[f] = sum over member edges only (ballot-driven, ~2.9 iters) ----
    float gv0 = 0.f, gv1 = 0.f;
    const float* aggb = g_agg + ((long)b * EE) * FF;
    while (mask0) {
        int e = __ffs(mask0) - 1; mask0 &= mask0 - 1;
        float ce = __shfl_sync(0xffffffffu, c0, e);
        float bt = __shfl_sync(0xffffffffu, bt0, e);
        float a0 = aggb[e * FF + f0], a1 = aggb[e * FF + f1];
        float v0 = fmaf(bt, h0 - a0, a0);
        float v1 = fmaf(bt, h1 - a1, a1);
        gv0 += ce * ((v0 > 0.f) ? v0 : expm1f(v0));
        gv1 += ce * ((v1 > 0.f) ? v1 : expm1f(v1));
    }
    while (mask1) {
        int e = __ffs(mask1) - 1; mask1 &= mask1 - 1;
        float ce = __shfl_sync(0xffffffffu, c1, e);
        float bt = __shfl_sync(0xffffffffu, bt1, e);
        int eg = e + 32;
        float a0 = aggb[eg * FF + f0], a1 = aggb[eg * FF + f1];
        float v0 = fmaf(bt, h0 - a0, a0);
        float v1 = fmaf(bt, h1 - a1, a1);
        gv0 += ce * ((v0 > 0.f) ? v0 : expm1f(v0));
        gv1 += ce * ((v1 > 0.f) ? v1 : expm1f(v1));
    }

    swig[w][f0] = make_float2(ind0, gv0);
    swig[w][f1] = make_float2(ind1, gv1);
    __syncwarp();

    float z1[4], z2[4];
    #pragma unroll
    for (int j = 0; j < 4; ++j) { z1[j] = sfcb[lane * 4 + j]; z2[j] = z1[j]; }
    #pragma unroll 4
    for (int f2 = 0; f2 < FF; ++f2) {
        float2 ig = swig[w][f2];
        float4 wv = *(const float4*)&sfc[f2 * FC + lane * 4];
        z1[0] += ig.x * wv.x; z1[1] += ig.x * wv.y; z1[2] += ig.x * wv.z; z1[3] += ig.x * wv.w;
        z2[0] += ig.y * wv.x; z2[1] += ig.y * wv.y; z2[2] += ig.y * wv.z; z2[3] += ig.y * wv.w;
    }
    float p1 = 0.f, p2 = 0.f;
    #pragma unroll
    for (int j = 0; j < 4; ++j) {
        float a = sav[lane * 4 + j];
        p1 += a * ftanh(z1[j]);
        p2 += a * ftanh(z2[j]);
    }
    #pragma unroll
    for (int o = 16; o; o >>= 1) {
        p1 += __shfl_xor_sync(0xffffffffu, p1, o);
        p2 += __shfl_xor_sync(0xffffffffu, p2, o);
    }

    float mm = fmaxf(p1, p2);
    float q1 = __expf(p1 - mm), q2 = __expf(p2 - mm);
    float cc = q1 / (q1 + q2);
    out[pair * FF + f0] = fmaf(cc, ind0 - gv0, gv0);
    out[pair * FF + f1] = fmaf(cc, ind1 - gv1, gv1);
}

// =======================================================================
// launcher
// =======================================================================
extern "C" void kernel_launch(void* const* d_in, const int* in_sizes, int n_in,
                              void* d_out, int out_size)
{
    const float* x   = (const float*)d_in[0];
    const float* H   = (const float*)d_in[1];
    const float* adj = (const float*)d_in[2];
    int wb = (n_in >= 12 && in_sizes[3] == 1) ? 4 : 3;
    const float* W      = (const float*)d_in[wb + 0];
    const float* W_ind  = (const float*)d_in[wb + 1];
    const float* a_node = (const float*)d_in[wb + 2];
    const float* a_gn   = (const float*)d_in[wb + 3];
    const float* a_ge   = (const float*)d_in[wb + 4];
    const float* fcW    = (const float*)d_in[wb + 5];
    const float* fcb    = (const float*)d_in[wb + 6];
    const float* av     = (const float*)d_in[wb + 7];
    float* out = (float*)d_out;

    k_h_emem<<<264 + 512, 256>>>(x, H, adj, W, W_ind, a_node, a_gn);
    k_edge<<<EE * BB, 512>>>(a_ge, fcW, fcb, av);
    k_final<<<(BB * NN) / 16, 512>>>(H, adj, fcW, fcb, av, out);
}